// round 7
// baseline (speedup 1.0000x reference)
#include <cuda_runtime.h>
#include <math.h>

#define C64 64
#define IMG 21
#define SLICES 7
#define DPS 63   // d-values per slice (7*63 = 441)

// ---------------- scratch (device globals; no allocations allowed) ----------
__device__ float g_k1s[2 * 441 * 64];                     // k1[b][pos][c]
__device__ float g_a1r[2 * 25 * 25 * 64];                 // att1 post-BN/ReLU [bg][o*64+c]
__device__ __align__(16) float g_Sw[2 * 25 * 64 * 64];    // window scores / normalized B [bg][c][c']
__device__ float g_pm[2 * 25 * SLICES * 64];              // partial max  [bg][slice][c]
__device__ float g_ps[2 * 25 * SLICES * 64];              // partial sum  [bg][slice][c]

// ---------------------------------------------------------------------------
// K1: per (b, g) block. Gathers the 64x25 x-tile for this group, computes
// k1 at the <=25 valid positions of this group (each k1 value belongs to
// exactly one group), then att1 = w1[g] @ kq followed by BN(eval)+ReLU.
// kq[i][c] for i<25 is xt.flat[i*64+c]; for i>=25 it is k1t.flat[(i-25)*64+c]
// (the reference's reshape chain is a pure flat reinterpretation).
// ---------------------------------------------------------------------------
__global__ void __launch_bounds__(256) k_front(
    const float* __restrict__ x,  const float* __restrict__ wk,
    const float* __restrict__ bk, const float* __restrict__ w1,
    const float* __restrict__ bng, const float* __restrict__ bnb,
    const float* __restrict__ bnm, const float* __restrict__ bnv)
{
    __shared__ float xt[1600];        // xt[ch*25 + ij]  (== flat[i'*64+c] view)
    __shared__ float k1t[1600];       // k1t[c*25 + ij]
    __shared__ float wks[25 * 128];   // wk[pos(ij), 157..283]
    __shared__ float w1s[1250];

    const int tid = threadIdx.x;
    const int b = blockIdx.x / 25, g = blockIdx.x % 25;
    const int ph = g / 5, pw = g % 5;

    for (int t = tid; t < 1250; t += 256) w1s[t] = w1[g * 1250 + t];
    for (int t = tid; t < 1600; t += 256) {
        int ch = t / 25, ij = t % 25;
        int row = (ij / 5) * 5 + ph, col = (ij % 5) * 5 + pw;
        xt[t] = (row < IMG && col < IMG) ? x[((b * C64 + ch) * IMG + row) * IMG + col] : 0.f;
    }
    for (int t = tid; t < 25 * 127; t += 256) {
        int ij = t / 127, idx = t - ij * 127;
        int row = (ij / 5) * 5 + ph, col = (ij % 5) * 5 + pw;
        if (row < IMG && col < IMG)
            wks[ij * 128 + idx] = wk[(row * IMG + col) * 441 + 157 + idx];
    }
    __syncthreads();

    // k1[b,c,pos] = bk[pos] + sum_{c'} x[b,c',pos] * wk[pos, 220 - c + c']
    for (int o = tid; o < 1600; o += 256) {
        int ij = o >> 6, c = o & 63;
        int row = (ij / 5) * 5 + ph, col = (ij % 5) * 5 + pw;
        float acc = 0.f;
        if (row < IMG && col < IMG) {
            int pos = row * IMG + col;
            acc = bk[pos];
            const float* wr = &wks[ij * 128 + 63 - c];   // wr[cp] = wk[pos, 220-c+cp]
            #pragma unroll 8
            for (int cp = 0; cp < 64; cp++)
                acc = fmaf(xt[cp * 25 + ij], wr[cp], acc);
            g_k1s[(b * 441 + pos) * 64 + c] = acc;
        }
        k1t[c * 25 + ij] = acc;   // zero-padded region stays 0 (k1_pad)
    }
    __syncthreads();

    // att1[o,c] = sum_i w1[g,o,i] * kq[i,c]; then BN + ReLU
    for (int o = tid; o < 1600; o += 256) {
        int orow = o >> 6, c = o & 63;
        const float* wr = &w1s[orow * 50];
        float acc = 0.f;
        #pragma unroll
        for (int i = 0; i < 25; i++) acc = fmaf(wr[i],      xt[i * 64 + c],  acc);
        #pragma unroll
        for (int i = 0; i < 25; i++) acc = fmaf(wr[25 + i], k1t[i * 64 + c], acc);
        int go = g * 25 + orow;
        float inv = bng[go] * rsqrtf(bnv[go] + 1e-5f);
        float v = (acc - bnm[go]) * inv + bnb[go];
        g_a1r[(b * 25 + g) * 1600 + o] = fmaxf(v, 0.f);
    }
}

// ---------------------------------------------------------------------------
// K2: att2 slice + online softmax partials. Block = (bg, slice of 63 d's).
// 256 threads = 4 d-subchunks x 64 columns. Each thread holds its att1r
// column in registers; w2 row broadcast from shared (float4).
// Stores raw scores for the 64-wide value window (d = 220-c+c') and (m,s).
// ---------------------------------------------------------------------------
__global__ void __launch_bounds__(256) k_att2(
    const float* __restrict__ w2, const float* __restrict__ b2)
{
    __shared__ __align__(16) float w2s[DPS * 28];  // row stride 28 -> 16B aligned
    __shared__ float b2s[DPS];
    __shared__ float rm[256], rs[256];

    const int tid = threadIdx.x;
    const int bg = blockIdx.x / SLICES, sl = blockIdx.x % SLICES;
    const int g = bg % 25;
    const int d0 = sl * DPS;

    for (int t = tid; t < DPS * 25; t += 256)
        w2s[(t / 25) * 28 + (t % 25)] = w2[g * 11025 + d0 * 25 + t];
    if (tid < DPS) b2s[tid] = b2[g * 441 + d0 + tid];
    __syncthreads();

    const int c = tid & 63, sub = tid >> 6;
    float myA[25];
    const float* ag = &g_a1r[bg * 1600 + c];
    #pragma unroll
    for (int i = 0; i < 25; i++) myA[i] = ag[i * 64];

    float m = -1e30f, s = 0.f;
    const int lo = 220 - c;
    float* swrow = &g_Sw[bg * 4096 + c * 64];
    for (int dd = sub; dd < DPS; dd += 4) {
        const float4* wr4 = reinterpret_cast<const float4*>(&w2s[dd * 28]);
        float val = b2s[dd];
        #pragma unroll
        for (int q = 0; q < 6; q++) {
            float4 f = wr4[q];
            val = fmaf(f.x, myA[4 * q],     val);
            val = fmaf(f.y, myA[4 * q + 1], val);
            val = fmaf(f.z, myA[4 * q + 2], val);
            val = fmaf(f.w, myA[4 * q + 3], val);
        }
        val = fmaf(w2s[dd * 28 + 24], myA[24], val);
        unsigned ci = (unsigned)(d0 + dd - lo);
        if (ci < 64u) swrow[ci] = val;       // each window entry written exactly once
        if (val > m) { s = s * __expf(m - val) + 1.f; m = val; }
        else         { s += __expf(val - m); }
    }
    rm[tid] = m; rs[tid] = s;
    __syncthreads();
    if (tid < 64) {
        float M = fmaxf(fmaxf(rm[tid], rm[64 + tid]), fmaxf(rm[128 + tid], rm[192 + tid]));
        float S = 0.f;
        #pragma unroll
        for (int k = 0; k < 4; k++) S += rs[k * 64 + tid] * __expf(rm[k * 64 + tid] - M);
        g_pm[(bg * SLICES + sl) * 64 + tid] = M;
        g_ps[(bg * SLICES + sl) * 64 + tid] = S;
    }
}

// ---------------------------------------------------------------------------
// K3: merge the 7 slice partials per (bg, c) and normalize the 64x64 window
// in place -> g_Sw now holds B[bg][c][c'] (softmax attention weights).
// ---------------------------------------------------------------------------
__global__ void __launch_bounds__(256) k_norm()
{
    __shared__ float Msh[64], Ish[64];
    const int bg = blockIdx.x;
    const int tid = threadIdx.x;
    if (tid < 64) {
        float M = -1e30f;
        #pragma unroll
        for (int k = 0; k < SLICES; k++) M = fmaxf(M, g_pm[(bg * SLICES + k) * 64 + tid]);
        float S = 0.f;
        #pragma unroll
        for (int k = 0; k < SLICES; k++)
            S += g_ps[(bg * SLICES + k) * 64 + tid] * __expf(g_pm[(bg * SLICES + k) * 64 + tid] - M);
        Msh[tid] = M; Ish[tid] = 1.f / S;
    }
    __syncthreads();
    float* sw = &g_Sw[bg * 4096];
    for (int t = tid; t < 4096; t += 256) {
        int c = t >> 6;
        sw[t] = __expf(sw[t] - Msh[c]) * Ish[c];
    }
}

// ---------------------------------------------------------------------------
// K4: final combine. Block per (b, h, w), thread per channel c.
// out = k1_pad[h+2,w+2] + [h,w>=2] * sum_{c'} v[b,c',h-2,w-2] * B[bg(h,w)][c][c']
// v is the depthwise 3x3 conv computed inline.
// ---------------------------------------------------------------------------
__global__ void __launch_bounds__(64) k_final(
    const float* __restrict__ x, const float* __restrict__ wv,
    const float* __restrict__ bv, float* __restrict__ out)
{
    const int blk = blockIdx.x;
    const int b = blk / 441, p = blk % 441;
    const int h = p / 21, w = p % 21;
    const int c = threadIdx.x;

    float res = 0.f;
    if (h < 19 && w < 19)   // k1_pad at (h+2, w+2); zero outside 21x21
        res = g_k1s[(b * 441 + (h + 2) * 21 + (w + 2)) * 64 + c];

    __shared__ __align__(16) float vsh[64];
    if (h >= 2 && w >= 2) {                 // value window needs p-4, q-4 >= 0
        const int y = h - 2, xq = w - 2;
        float acc = bv[c];
        #pragma unroll
        for (int dy = 0; dy < 3; dy++) {
            int r = y + dy - 1;             // r <= 19 < 21 always
            #pragma unroll
            for (int dx = 0; dx < 3; dx++) {
                int cc = xq + dx - 1;       // cc <= 19 < 21 always
                if (r >= 0 && cc >= 0)
                    acc = fmaf(x[((b * C64 + c) * IMG + r) * IMG + cc],
                               wv[c * 9 + dy * 3 + dx], acc);
            }
        }
        vsh[c] = acc;
        __syncthreads();                    // uniform branch per block
        const int g = 5 * ((h + 2) % 5) + ((w + 2) % 5);
        const float4* Br = reinterpret_cast<const float4*>(&g_Sw[((b * 25 + g) * 64 + c) * 64]);
        const float4* Vr = reinterpret_cast<const float4*>(vsh);
        float s0 = 0.f, s1 = 0.f;
        #pragma unroll
        for (int k = 0; k < 16; k += 2) {
            float4 bb = Br[k],     vv = Vr[k];
            s0 += bb.x * vv.x + bb.y * vv.y + bb.z * vv.z + bb.w * vv.w;
            float4 bb2 = Br[k + 1], vv2 = Vr[k + 1];
            s1 += bb2.x * vv2.x + bb2.y * vv2.y + bb2.z * vv2.z + bb2.w * vv2.w;
        }
        res += s0 + s1;
    }
    out[((b * C64 + c) * IMG + h) * IMG + w] = res;
}

// ---------------------------------------------------------------------------
extern "C" void kernel_launch(void* const* d_in, const int* in_sizes, int n_in,
                              void* d_out, int out_size)
{
    const float* x   = (const float*)d_in[0];
    const float* wk  = (const float*)d_in[1];
    const float* bk  = (const float*)d_in[2];
    const float* w1  = (const float*)d_in[3];
    const float* bng = (const float*)d_in[4];
    const float* bnb = (const float*)d_in[5];
    const float* bnm = (const float*)d_in[6];
    const float* bnv = (const float*)d_in[7];
    const float* w2  = (const float*)d_in[8];
    const float* b2  = (const float*)d_in[9];
    const float* wv  = (const float*)d_in[10];
    const float* bv  = (const float*)d_in[11];
    float* out = (float*)d_out;

    k_front<<<50, 256>>>(x, wk, bk, w1, bng, bnb, bnm, bnv);
    k_att2<<<50 * SLICES, 256>>>(w2, b2);
    k_norm<<<50, 256>>>();
    k_final<<<882, 64>>>(x, wv, bv, out);
}

// round 8
// speedup vs baseline: 1.4522x; 1.4522x over previous
#include <cuda_runtime.h>
#include <math.h>

#define C64 64
#define IMG 21
#define SLICES 7
#define DPS 63   // d-values per slice (7*63 = 441)

// ---------------- scratch (device globals; no allocations allowed) ----------
__device__ float g_k1s[2 * 441 * 64];                     // k1[b][pos][c]
__device__ float g_a1r[2 * 25 * 25 * 64];                 // att1 post-BN/ReLU [bg][o*64+c]
__device__ __align__(16) float g_Sw[2 * 25 * 64 * 64];    // TRANSPOSED: scores/B [bg][c'][c]
__device__ float g_pm[2 * 25 * SLICES * 64];              // partial max  [bg][slice][c]
__device__ float g_ps[2 * 25 * SLICES * 64];              // partial sum  [bg][slice][c]

// ---------------------------------------------------------------------------
// K1: one block per (b, pos). k1[b,pos,c] = bk[pos] + sum_cp x[b,cp,pos] *
// wk[pos, 220-c+cp].  Full-chip grid (882 blocks), all operands staged in smem.
// ---------------------------------------------------------------------------
__global__ void __launch_bounds__(64) k_k1(
    const float* __restrict__ x, const float* __restrict__ wk,
    const float* __restrict__ bk)
{
    __shared__ float xcol[64];
    __shared__ float wkrow[127];   // wk[pos, 157..283]
    const int blk = blockIdx.x;
    const int b = blk / 441, pos = blk % 441;
    const int c = threadIdx.x;

    xcol[c] = x[(b * C64 + c) * 441 + pos];
    for (int t = c; t < 127; t += 64) wkrow[t] = wk[pos * 441 + 157 + t];
    __syncthreads();

    float acc = bk[pos];
    const float* wr = &wkrow[63 - c];          // wr[cp] = wk[pos, 220-c+cp]
    #pragma unroll 16
    for (int cp = 0; cp < 64; cp++) acc = fmaf(xcol[cp], wr[cp], acc);
    g_k1s[(b * 441 + pos) * 64 + c] = acc;
}

// ---------------------------------------------------------------------------
// ATT1: block = (bg, oc) with oc one of 5 chunks of 5 o-rows. 320 threads.
// kq[i][c] (i<25: x-tile flat, i>=25: k1-tile flat; flat idx f=i*64+c maps to
// channel ch=f/25, tile pos ij=f%25 of the (ph,pw) strided gather).
// att1 = w1[g] @ kq, then BN(eval)+ReLU -> g_a1r.
// ---------------------------------------------------------------------------
__global__ void __launch_bounds__(320) k_att1(
    const float* __restrict__ x,  const float* __restrict__ w1,
    const float* __restrict__ bng, const float* __restrict__ bnb,
    const float* __restrict__ bnm, const float* __restrict__ bnv)
{
    __shared__ float kqs[50 * 64];   // kqs[i*64+c]
    __shared__ float w1s[5 * 50];

    const int tid = threadIdx.x;
    const int blk = blockIdx.x;
    const int bg = blk / 5, oc = blk % 5;
    const int b = bg / 25, g = bg % 25;
    const int ph = g / 5, pw = g % 5;

    for (int t = tid; t < 250; t += 320) w1s[t] = w1[g * 1250 + oc * 250 + t];
    for (int f = tid; f < 3200; f += 320) {
        int f2 = (f < 1600) ? f : f - 1600;
        int ch = f2 / 25, ij = f2 % 25;
        int row = (ij / 5) * 5 + ph, col = (ij % 5) * 5 + pw;
        float v = 0.f;
        if (row < IMG && col < IMG) {
            int pos = row * IMG + col;
            v = (f < 1600) ? x[((b * C64 + ch) * IMG + row) * IMG + col]
                           : g_k1s[(b * 441 + pos) * 64 + ch];
        }
        kqs[f] = v;
    }
    __syncthreads();

    const int lrow = tid / 64, c = tid & 63;   // 5 o-rows x 64 c
    const float* wr = &w1s[lrow * 50];
    float acc = 0.f;
    #pragma unroll
    for (int i = 0; i < 50; i++) acc = fmaf(wr[i], kqs[i * 64 + c], acc);

    const int orow = oc * 5 + lrow;
    const int go = g * 25 + orow;
    float inv = bng[go] * rsqrtf(bnv[go] + 1e-5f);
    float v = (acc - bnm[go]) * inv + bnb[go];
    g_a1r[bg * 1600 + orow * 64 + c] = fmaxf(v, 0.f);
}

// ---------------------------------------------------------------------------
// K2: att2 slice + online softmax partials. Block = (bg, slice of 63 d's).
// 256 threads = 4 d-subchunks x 64 columns. Stores raw scores for the 64-wide
// value window (d = 220-c+c') TRANSPOSED as g_Sw[bg][c'][c], plus (m,s).
// ---------------------------------------------------------------------------
__global__ void __launch_bounds__(256) k_att2(
    const float* __restrict__ w2, const float* __restrict__ b2)
{
    __shared__ __align__(16) float w2s[DPS * 28];  // row stride 28 -> 16B aligned
    __shared__ float b2s[DPS];
    __shared__ float rm[256], rs[256];

    const int tid = threadIdx.x;
    const int bg = blockIdx.x / SLICES, sl = blockIdx.x % SLICES;
    const int g = bg % 25;
    const int d0 = sl * DPS;

    for (int t = tid; t < DPS * 25; t += 256)
        w2s[(t / 25) * 28 + (t % 25)] = w2[g * 11025 + d0 * 25 + t];
    if (tid < DPS) b2s[tid] = b2[g * 441 + d0 + tid];
    __syncthreads();

    const int c = tid & 63, sub = tid >> 6;
    float myA[25];
    const float* ag = &g_a1r[bg * 1600 + c];
    #pragma unroll
    for (int i = 0; i < 25; i++) myA[i] = ag[i * 64];

    float m = -1e30f, s = 0.f;
    const int lo = 220 - c;
    float* swbase = &g_Sw[bg * 4096];
    for (int dd = sub; dd < DPS; dd += 4) {
        const float4* wr4 = reinterpret_cast<const float4*>(&w2s[dd * 28]);
        float val = b2s[dd];
        #pragma unroll
        for (int q = 0; q < 6; q++) {
            float4 f = wr4[q];
            val = fmaf(f.x, myA[4 * q],     val);
            val = fmaf(f.y, myA[4 * q + 1], val);
            val = fmaf(f.z, myA[4 * q + 2], val);
            val = fmaf(f.w, myA[4 * q + 3], val);
        }
        val = fmaf(w2s[dd * 28 + 24], myA[24], val);
        unsigned ci = (unsigned)(d0 + dd - lo);
        if (ci < 64u) swbase[ci * 64 + c] = val;   // transposed, written once
        if (val > m) { s = s * __expf(m - val) + 1.f; m = val; }
        else         { s += __expf(val - m); }
    }
    rm[tid] = m; rs[tid] = s;
    __syncthreads();
    if (tid < 64) {
        float M = fmaxf(fmaxf(rm[tid], rm[64 + tid]), fmaxf(rm[128 + tid], rm[192 + tid]));
        float S = 0.f;
        #pragma unroll
        for (int k = 0; k < 4; k++) S += rs[k * 64 + tid] * __expf(rm[k * 64 + tid] - M);
        g_pm[(bg * SLICES + sl) * 64 + tid] = M;
        g_ps[(bg * SLICES + sl) * 64 + tid] = S;
    }
}

// ---------------------------------------------------------------------------
// K3: merge slice partials per (bg,c), normalize the transposed 64x64 window
// in place. Block = (bg, quarter of the 4096 elements).
// ---------------------------------------------------------------------------
__global__ void __launch_bounds__(256) k_norm()
{
    __shared__ float Msh[64], Ish[64];
    const int bg = blockIdx.x >> 2, chunk = blockIdx.x & 3;
    const int tid = threadIdx.x;
    if (tid < 64) {
        float M = -1e30f;
        #pragma unroll
        for (int k = 0; k < SLICES; k++) M = fmaxf(M, g_pm[(bg * SLICES + k) * 64 + tid]);
        float S = 0.f;
        #pragma unroll
        for (int k = 0; k < SLICES; k++)
            S += g_ps[(bg * SLICES + k) * 64 + tid] * __expf(g_pm[(bg * SLICES + k) * 64 + tid] - M);
        Msh[tid] = M; Ish[tid] = 1.f / S;
    }
    __syncthreads();
    float* sw = &g_Sw[bg * 4096 + chunk * 1024];
    for (int t = tid; t < 1024; t += 256) {
        int c = t & 63;                       // transposed layout: [c'*64 + c]
        sw[t] = __expf(sw[t] - Msh[c]) * Ish[c];
    }
}

// ---------------------------------------------------------------------------
// K4: final combine. Block per (b,h,w), 256 threads: tid = q*64+c, q-th
// quarter handles c' in [16q,16q+16). Coalesced reads of transposed B rows.
// out = k1_pad[h+2,w+2] + [h,w>=2] * sum_{c'} v[b,c',h-2,w-2]*B[bg][c'][c]
// ---------------------------------------------------------------------------
__global__ void __launch_bounds__(256) k_final(
    const float* __restrict__ x, const float* __restrict__ wv,
    const float* __restrict__ bv, float* __restrict__ out)
{
    __shared__ float vsh[64];
    __shared__ float part[256];

    const int blk = blockIdx.x;
    const int b = blk / 441, p = blk % 441;
    const int h = p / 21, w = p % 21;
    const int tid = threadIdx.x;
    const int c = tid & 63, q = tid >> 6;

    const bool hasv = (h >= 2 && w >= 2);     // uniform per block
    if (hasv && q == 0) {                     // depthwise 3x3 conv value
        const int y = h - 2, xq = w - 2;
        float acc = bv[c];
        #pragma unroll
        for (int dy = 0; dy < 3; dy++) {
            int r = y + dy - 1;
            #pragma unroll
            for (int dx = 0; dx < 3; dx++) {
                int cc = xq + dx - 1;
                if (r >= 0 && cc >= 0)
                    acc = fmaf(x[((b * C64 + c) * IMG + r) * IMG + cc],
                               wv[c * 9 + dy * 3 + dx], acc);
            }
        }
        vsh[c] = acc;
    }
    __syncthreads();

    float partial = 0.f;
    if (hasv) {
        const int g = 5 * ((h + 2) % 5) + ((w + 2) % 5);
        const float* Bt = &g_Sw[(b * 25 + g) * 4096];
        #pragma unroll
        for (int j = 0; j < 16; j++) {
            int cp = q * 16 + j;
            partial = fmaf(Bt[cp * 64 + c], vsh[cp], partial);  // coalesced
        }
    }
    part[tid] = partial;
    __syncthreads();

    if (q == 0) {
        float res = part[c] + part[64 + c] + part[128 + c] + part[192 + c];
        if (h < 19 && w < 19)
            res += g_k1s[(b * 441 + (h + 2) * 21 + (w + 2)) * 64 + c];
        out[((b * C64 + c) * IMG + h) * IMG + w] = res;
    }
}

// ---------------------------------------------------------------------------
extern "C" void kernel_launch(void* const* d_in, const int* in_sizes, int n_in,
                              void* d_out, int out_size)
{
    const float* x   = (const float*)d_in[0];
    const float* wk  = (const float*)d_in[1];
    const float* bk  = (const float*)d_in[2];
    const float* w1  = (const float*)d_in[3];
    const float* bng = (const float*)d_in[4];
    const float* bnb = (const float*)d_in[5];
    const float* bnm = (const float*)d_in[6];
    const float* bnv = (const float*)d_in[7];
    const float* w2  = (const float*)d_in[8];
    const float* b2  = (const float*)d_in[9];
    const float* wv  = (const float*)d_in[10];
    const float* bv  = (const float*)d_in[11];
    float* out = (float*)d_out;

    k_k1  <<<882, 64>>>(x, wk, bk);
    k_att1<<<250, 320>>>(x, w1, bng, bnb, bnm, bnv);
    k_att2<<<50 * SLICES, 256>>>(w2, b2);
    k_norm<<<200, 256>>>();
    k_final<<<882, 256>>>(x, wv, bv, out);
}